// round 1
// baseline (speedup 1.0000x reference)
#include <cuda_runtime.h>

// FakeReviewGNN: 2-layer GCN, N=100000 nodes, features 7 -> 64 -> 32 -> 2.
// out[v] = dinv[v] * (sum_{e: src->v} g[src] + g[v]) + b, with g = (h @ W) * dinv.
// Self-loop folded into accumulator init; edge kernel is pure gather + red.add.

#define MAXN 100000
#define F1 64
#define F2 32

// Scratch (allocation-free: __device__ globals)
__device__ float d_deg [MAXN];
__device__ float d_dinv[MAXN];
__device__ float d_g1  [MAXN * F1];
__device__ float d_s1  [MAXN * F1];
__device__ float d_g2  [MAXN * F2];
__device__ float d_s2  [MAXN * F2];

__device__ __forceinline__ void red_add_v4(float4* addr, float4 v) {
    asm volatile("red.global.add.v4.f32 [%0], {%1, %2, %3, %4};"
                 :: "l"(addr), "f"(v.x), "f"(v.y), "f"(v.z), "f"(v.w)
                 : "memory");
}

// ---- degree / normalization -------------------------------------------------

__global__ void k_deg_init(int n) {
    int i = blockIdx.x * blockDim.x + threadIdx.x;
    if (i < n) d_deg[i] = 1.0f;  // self-loop contribution
}

__global__ void k_deg_edges(const int* __restrict__ dst, int E) {
    int i = blockIdx.x * blockDim.x + threadIdx.x;
    if (i < E) atomicAdd(&d_deg[dst[i]], 1.0f);
}

__global__ void k_dinv(int n) {
    int i = blockIdx.x * blockDim.x + threadIdx.x;
    if (i < n) d_dinv[i] = rsqrtf(d_deg[i]);  // deg >= 1 always
}

// ---- layer 1 dense transform: g1 = (x @ W1) * dinv; s1 = g1 (self loop) ----

__global__ void k_l1_transform(const float* __restrict__ x,
                               const float* __restrict__ W1, int n) {
    __shared__ float Ws[7 * F1];
    for (int i = threadIdx.x; i < 7 * F1; i += blockDim.x) Ws[i] = W1[i];
    __syncthreads();

    int t = blockIdx.x * blockDim.x + threadIdx.x;
    int node = t >> 6;          // 64 threads per node
    int f    = t & 63;
    if (node >= n) return;

    float acc = 0.0f;
    #pragma unroll
    for (int k = 0; k < 7; k++)
        acc += x[node * 7 + k] * Ws[k * F1 + f];  // x reads are warp-uniform -> broadcast

    float g = acc * d_dinv[node];
    d_g1[node * F1 + f] = g;
    d_s1[node * F1 + f] = g;
}

// ---- edge scatter (F=64): s1[dst] += g1[src], vector red.add ----------------

__global__ void k_scatter64(const int* __restrict__ src,
                            const int* __restrict__ dst, int E) {
    long long idx = (long long)blockIdx.x * blockDim.x + threadIdx.x;
    int e = (int)(idx >> 4);    // 16 float4 chunks per edge (64 floats)
    int c = (int)(idx & 15);
    if (e >= E) return;
    int u = src[e], v = dst[e];
    float4 val = reinterpret_cast<const float4*>(d_g1)[(long long)u * 16 + c];
    red_add_v4(&reinterpret_cast<float4*>(d_s1)[(long long)v * 16 + c], val);
}

// ---- layer 2: h1 = relu(dinv*s1 + b1); g2 = (h1 @ W2) * dinv; s2 = g2 ------

__global__ void k_l2_transform(const float* __restrict__ W2,
                               const float* __restrict__ b1, int n) {
    __shared__ float W2s[F1 * F2];       // 8 KB
    __shared__ float hs[8][F1];          // 8 nodes per block, one warp each
    for (int i = threadIdx.x; i < F1 * F2; i += blockDim.x) W2s[i] = W2[i];
    __syncthreads();

    int warp = threadIdx.x >> 5;
    int lane = threadIdx.x & 31;
    int node = blockIdx.x * 8 + warp;
    if (node >= n) return;

    float dv = d_dinv[node];
    float a0 = d_s1[node * F1 + lane];
    float a1 = d_s1[node * F1 + 32 + lane];
    hs[warp][lane]      = fmaxf(dv * a0 + b1[lane],      0.0f);
    hs[warp][lane + 32] = fmaxf(dv * a1 + b1[lane + 32], 0.0f);
    __syncwarp();

    float acc = 0.0f;
    #pragma unroll
    for (int k = 0; k < F1; k++)
        acc += hs[warp][k] * W2s[k * F2 + lane];  // broadcast + conflict-free

    float g = acc * dv;
    d_g2[node * F2 + lane] = g;
    d_s2[node * F2 + lane] = g;
}

// ---- edge scatter (F=32) ----------------------------------------------------

__global__ void k_scatter32(const int* __restrict__ src,
                            const int* __restrict__ dst, int E) {
    long long idx = (long long)blockIdx.x * blockDim.x + threadIdx.x;
    int e = (int)(idx >> 3);    // 8 float4 chunks per edge (32 floats)
    int c = (int)(idx & 7);
    if (e >= E) return;
    int u = src[e], v = dst[e];
    float4 val = reinterpret_cast<const float4*>(d_g2)[(long long)u * 8 + c];
    red_add_v4(&reinterpret_cast<float4*>(d_s2)[(long long)v * 8 + c], val);
}

// ---- final: h2 = relu(dinv*s2 + b2); logits = h2 @ Wc + bc; log_softmax ----

__global__ void k_final(const float* __restrict__ b2,
                        const float* __restrict__ Wc,
                        const float* __restrict__ bc,
                        float* __restrict__ out, int n) {
    int node = blockIdx.x * blockDim.x + threadIdx.x;
    if (node >= n) return;

    float dv = d_dinv[node];
    float l0 = bc[0], l1 = bc[1];
    #pragma unroll
    for (int k = 0; k < F2; k++) {
        float h = fmaxf(dv * d_s2[node * F2 + k] + b2[k], 0.0f);
        l0 += h * Wc[k * 2];
        l1 += h * Wc[k * 2 + 1];
    }
    float m   = fmaxf(l0, l1);
    float lse = m + logf(expf(l0 - m) + expf(l1 - m));
    out[node * 2]     = l0 - lse;
    out[node * 2 + 1] = l1 - lse;
}

// ---- launch -----------------------------------------------------------------

extern "C" void kernel_launch(void* const* d_in, const int* in_sizes, int n_in,
                              void* d_out, int out_size) {
    const float* x  = (const float*)d_in[0];
    const int*   ei = (const int*)  d_in[1];
    const float* W1 = (const float*)d_in[2];
    const float* b1 = (const float*)d_in[3];
    const float* W2 = (const float*)d_in[4];
    const float* b2 = (const float*)d_in[5];
    const float* Wc = (const float*)d_in[6];
    const float* bc = (const float*)d_in[7];
    float* out = (float*)d_out;

    int n = in_sizes[0] / 7;         // 100000
    int E = in_sizes[1] / 2;         // 1600000
    const int* src = ei;
    const int* dst = ei + E;

    const int T = 256;

    k_deg_init <<<(n + T - 1) / T, T>>>(n);
    k_deg_edges<<<(E + T - 1) / T, T>>>(dst, E);
    k_dinv     <<<(n + T - 1) / T, T>>>(n);

    k_l1_transform<<<((long long)n * 64 + T - 1) / T, T>>>(x, W1, n);

    long long w1 = (long long)E * 16;
    k_scatter64<<<(unsigned)((w1 + T - 1) / T), T>>>(src, dst, E);

    k_l2_transform<<<(n + 7) / 8, T>>>(W2, b1, n);

    long long w2 = (long long)E * 8;
    k_scatter32<<<(unsigned)((w2 + T - 1) / T), T>>>(src, dst, E);

    k_final<<<(n + T - 1) / T, T>>>(b2, Wc, bc, out, n);
}

// round 2
// speedup vs baseline: 1.6234x; 1.6234x over previous
#include <cuda_runtime.h>

// FakeReviewGNN: 2-layer GCN, N=100000, features 7 -> 64 -> 32 -> 2.
// Layer-1 aggregation done in 7-dim INPUT space (W1 commutes with edge-sum):
//   p[v] = xd[v] + sum_{src->v} xd[src],  xd = x * dinv      (8 floats/edge padded)
//   h1[v] = relu(dinv[v] * (p[v] @ W1) + b1)
//   g2[v] = (h1[v] @ W2) * dinv[v];  s2[v] = g2[v] + sum g2[src]   (32 floats/edge)
//   out[v] = log_softmax(relu(dinv[v]*s2[v] + b2) @ Wc + bc)

#define MAXN 100000
#define F1 64
#define F2 32

__device__ float d_deg [MAXN];
__device__ float d_dinv[MAXN];
__device__ float d_xd  [MAXN * 8];   // x * dinv, padded 7 -> 8
__device__ float d_p   [MAXN * 8];   // aggregated input-space messages
__device__ float d_g2  [MAXN * F2];
__device__ float d_s2  [MAXN * F2];

__device__ __forceinline__ void red_add_v4(float4* addr, float4 v) {
    asm volatile("red.global.add.v4.f32 [%0], {%1, %2, %3, %4};"
                 :: "l"(addr), "f"(v.x), "f"(v.y), "f"(v.z), "f"(v.w)
                 : "memory");
}

// ---- degree ----------------------------------------------------------------

__global__ void k_deg_init(int n) {
    int i = blockIdx.x * blockDim.x + threadIdx.x;
    if (i < n) d_deg[i] = 1.0f;  // self-loop
}

__global__ void k_deg_edges(const int* __restrict__ dst, int E) {
    int i = blockIdx.x * blockDim.x + threadIdx.x;
    if (i < E) atomicAdd(&d_deg[dst[i]], 1.0f);
}

// ---- prep: dinv, xd = x*dinv (pad to 8), p init = xd (self loop) -----------

__global__ void k_prep(const float* __restrict__ x, int n) {
    int i = blockIdx.x * blockDim.x + threadIdx.x;
    if (i >= n) return;
    float dv = rsqrtf(d_deg[i]);   // deg >= 1
    d_dinv[i] = dv;
    const float* xi = x + (long long)i * 7;
    float4 a, b;
    a.x = xi[0] * dv; a.y = xi[1] * dv; a.z = xi[2] * dv; a.w = xi[3] * dv;
    b.x = xi[4] * dv; b.y = xi[5] * dv; b.z = xi[6] * dv; b.w = 0.0f;
    reinterpret_cast<float4*>(d_xd)[i * 2]     = a;
    reinterpret_cast<float4*>(d_xd)[i * 2 + 1] = b;
    reinterpret_cast<float4*>(d_p )[i * 2]     = a;
    reinterpret_cast<float4*>(d_p )[i * 2 + 1] = b;
}

// ---- edge scatter in input space: p[dst] += xd[src]  (2 x red.v4 / edge) ---

__global__ void k_scatter7(const int* __restrict__ src,
                           const int* __restrict__ dst, int E) {
    long long idx = (long long)blockIdx.x * blockDim.x + threadIdx.x;
    int e = (int)(idx >> 1);
    int c = (int)(idx & 1);
    if (e >= E) return;
    int u = src[e], v = dst[e];
    float4 val = reinterpret_cast<const float4*>(d_xd)[(long long)u * 2 + c];
    red_add_v4(&reinterpret_cast<float4*>(d_p)[(long long)v * 2 + c], val);
}

// ---- fused transform: h1 = relu(dinv*(p@W1)+b1); g2 = (h1@W2)*dinv ---------
// one warp per node, 8 nodes per 256-thread block

__global__ void k_transform(const float* __restrict__ W1,
                            const float* __restrict__ b1,
                            const float* __restrict__ W2, int n) {
    __shared__ float W1s[7 * F1];     // 448
    __shared__ float b1s[F1];         // 64
    __shared__ float W2s[F1 * F2];    // 2048
    __shared__ float hs[8][F1];       // 512

    for (int i = threadIdx.x; i < 7 * F1; i += blockDim.x) W1s[i] = W1[i];
    for (int i = threadIdx.x; i < F1;     i += blockDim.x) b1s[i] = b1[i];
    for (int i = threadIdx.x; i < F1 * F2; i += blockDim.x) W2s[i] = W2[i];
    __syncthreads();

    int warp = threadIdx.x >> 5;
    int lane = threadIdx.x & 31;
    int node = blockIdx.x * 8 + warp;
    if (node >= n) return;

    float dv = d_dinv[node];
    float pv = (lane < 8) ? d_p[node * 8 + lane] : 0.0f;

    float a0 = 0.0f, a1 = 0.0f;
    #pragma unroll
    for (int k = 0; k < 7; k++) {
        float pk = __shfl_sync(0xffffffffu, pv, k);
        a0 += pk * W1s[k * F1 + lane];
        a1 += pk * W1s[k * F1 + 32 + lane];
    }
    hs[warp][lane]      = fmaxf(dv * a0 + b1s[lane],      0.0f);
    hs[warp][lane + 32] = fmaxf(dv * a1 + b1s[lane + 32], 0.0f);
    __syncwarp();

    float acc = 0.0f;
    #pragma unroll
    for (int k = 0; k < F1; k++)
        acc += hs[warp][k] * W2s[k * F2 + lane];  // hs broadcast, W2s conflict-free

    float g = acc * dv;
    d_g2[node * F2 + lane] = g;
    d_s2[node * F2 + lane] = g;   // self-loop init
}

// ---- edge scatter (F=32): s2[dst] += g2[src]  (8 x red.v4 / edge) ----------

__global__ void k_scatter32(const int* __restrict__ src,
                            const int* __restrict__ dst, int E) {
    long long idx = (long long)blockIdx.x * blockDim.x + threadIdx.x;
    int e = (int)(idx >> 3);
    int c = (int)(idx & 7);
    if (e >= E) return;
    int u = src[e], v = dst[e];
    float4 val = reinterpret_cast<const float4*>(d_g2)[(long long)u * 8 + c];
    red_add_v4(&reinterpret_cast<float4*>(d_s2)[(long long)v * 8 + c], val);
}

// ---- final: relu + classifier + log_softmax --------------------------------

__global__ void k_final(const float* __restrict__ b2,
                        const float* __restrict__ Wc,
                        const float* __restrict__ bc,
                        float* __restrict__ out, int n) {
    int node = blockIdx.x * blockDim.x + threadIdx.x;
    if (node >= n) return;

    float dv = d_dinv[node];
    float l0 = bc[0], l1 = bc[1];
    #pragma unroll
    for (int k = 0; k < F2; k++) {
        float h = fmaxf(dv * d_s2[node * F2 + k] + b2[k], 0.0f);
        l0 += h * Wc[k * 2];
        l1 += h * Wc[k * 2 + 1];
    }
    float m   = fmaxf(l0, l1);
    float lse = m + logf(expf(l0 - m) + expf(l1 - m));
    out[node * 2]     = l0 - lse;
    out[node * 2 + 1] = l1 - lse;
}

// ---- launch ----------------------------------------------------------------

extern "C" void kernel_launch(void* const* d_in, const int* in_sizes, int n_in,
                              void* d_out, int out_size) {
    const float* x  = (const float*)d_in[0];
    const int*   ei = (const int*)  d_in[1];
    const float* W1 = (const float*)d_in[2];
    const float* b1 = (const float*)d_in[3];
    const float* W2 = (const float*)d_in[4];
    const float* b2 = (const float*)d_in[5];
    const float* Wc = (const float*)d_in[6];
    const float* bc = (const float*)d_in[7];
    float* out = (float*)d_out;

    int n = in_sizes[0] / 7;         // 100000
    int E = in_sizes[1] / 2;         // 1600000
    const int* src = ei;
    const int* dst = ei + E;

    const int T = 256;

    k_deg_init <<<(n + T - 1) / T, T>>>(n);
    k_deg_edges<<<(E + T - 1) / T, T>>>(dst, E);
    k_prep     <<<(n + T - 1) / T, T>>>(x, n);

    long long w1 = (long long)E * 2;
    k_scatter7<<<(unsigned)((w1 + T - 1) / T), T>>>(src, dst, E);

    k_transform<<<(n + 7) / 8, T>>>(W1, b1, W2, n);

    long long w2 = (long long)E * 8;
    k_scatter32<<<(unsigned)((w2 + T - 1) / T), T>>>(src, dst, E);

    k_final<<<(n + T - 1) / T, T>>>(b2, Wc, bc, out, n);
}

// round 3
// speedup vs baseline: 1.6706x; 1.0291x over previous
#include <cuda_runtime.h>

// FakeReviewGNN: 2-layer GCN, N=100000, 7 -> 64 -> 32 -> 2.
// Per-call CSR (counting sort by dst) -> atomic-free gather aggregation.
//   cnt[v]    = #incoming edges; dinv = rsqrt(cnt+1)
//   rowptr    = exclusive_scan(cnt); col[rowptr[v]..] = src of edges into v
//   xd        = x * dinv (padded 7->8)
//   transform: p = xd[v] + sum_nb xd[nb];  h1 = relu(dinv*(p@W1)+b1);
//              g2 = (h1@W2)*dinv
//   final:     s = g2[v] + sum_nb g2[nb];  h2 = relu(dinv*s+b2);
//              out = log_softmax(h2@Wc + bc)

#define MAXN 100000
#define MAXE 1600000
#define F1 64
#define F2 32

#define SCAN_T 256
#define SCAN_C 4
#define SCAN_CHUNK (SCAN_T * SCAN_C)   // 1024

__device__ int   d_cnt   [MAXN];
__device__ int   d_rowptr[MAXN + 1];
__device__ int   d_wcur  [MAXN];
__device__ int   d_bsum  [128];
__device__ int   d_boff  [128];
__device__ int   d_col   [MAXE];
__device__ float d_dinv  [MAXN];
__device__ __align__(128) float d_xd[MAXN * 8];
__device__ __align__(128) float d_g2[MAXN * F2];

// ---- histogram -------------------------------------------------------------

__global__ void k_zero_cnt(int n) {
    int i = blockIdx.x * blockDim.x + threadIdx.x;
    if (i < n) d_cnt[i] = 0;
}

__global__ void k_count(const int* __restrict__ dst, int E) {
    int i = blockIdx.x * blockDim.x + threadIdx.x;
    if (i < E) atomicAdd(&d_cnt[dst[i]], 1);
}

// ---- exclusive scan (3 phases) ---------------------------------------------

__global__ void k_scan_partial(int n) {
    __shared__ int sh[SCAN_T];
    int base = blockIdx.x * SCAN_CHUNK + threadIdx.x * SCAN_C;
    int s = 0;
    #pragma unroll
    for (int j = 0; j < SCAN_C; j++) {
        int idx = base + j;
        if (idx < n) s += d_cnt[idx];
    }
    sh[threadIdx.x] = s;
    __syncthreads();
    for (int off = SCAN_T / 2; off > 0; off >>= 1) {
        if (threadIdx.x < off) sh[threadIdx.x] += sh[threadIdx.x + off];
        __syncthreads();
    }
    if (threadIdx.x == 0) d_bsum[blockIdx.x] = sh[0];
}

__global__ void k_scan_top(int nblk, int n, int E) {
    __shared__ int sh[128];
    int tid = threadIdx.x;
    int v = (tid < nblk) ? d_bsum[tid] : 0;
    sh[tid] = v;
    __syncthreads();
    for (int off = 1; off < 128; off <<= 1) {
        int t = (tid >= off) ? sh[tid - off] : 0;
        __syncthreads();
        sh[tid] += t;
        __syncthreads();
    }
    if (tid < nblk) d_boff[tid] = sh[tid] - v;   // exclusive
    if (tid == 0) d_rowptr[n] = E;
}

__global__ void k_scan_apply(int n) {
    __shared__ int sh[SCAN_T];
    int tid = threadIdx.x;
    int base = blockIdx.x * SCAN_CHUNK + tid * SCAN_C;
    int loc[SCAN_C];
    int s = 0;
    #pragma unroll
    for (int j = 0; j < SCAN_C; j++) {
        int idx = base + j;
        loc[j] = (idx < n) ? d_cnt[idx] : 0;
        s += loc[j];
    }
    sh[tid] = s;
    __syncthreads();
    for (int off = 1; off < SCAN_T; off <<= 1) {
        int t = (tid >= off) ? sh[tid - off] : 0;
        __syncthreads();
        sh[tid] += t;
        __syncthreads();
    }
    int run = d_boff[blockIdx.x] + sh[tid] - s;  // exclusive prefix
    #pragma unroll
    for (int j = 0; j < SCAN_C; j++) {
        int idx = base + j;
        if (idx < n) {
            d_rowptr[idx] = run;
            d_wcur[idx]   = run;
            run += loc[j];
        }
    }
}

// ---- CSR fill + prep -------------------------------------------------------

__global__ void k_fill(const int* __restrict__ src,
                       const int* __restrict__ dst, int E) {
    int e = blockIdx.x * blockDim.x + threadIdx.x;
    if (e >= E) return;
    int v = dst[e];
    int pos = atomicAdd(&d_wcur[v], 1);
    d_col[pos] = src[e];
}

__global__ void k_prep(const float* __restrict__ x, int n) {
    int i = blockIdx.x * blockDim.x + threadIdx.x;
    if (i >= n) return;
    float dv = rsqrtf((float)(d_cnt[i] + 1));   // +1 self loop
    d_dinv[i] = dv;
    const float* xi = x + (long long)i * 7;
    float4 a, b;
    a.x = xi[0] * dv; a.y = xi[1] * dv; a.z = xi[2] * dv; a.w = xi[3] * dv;
    b.x = xi[4] * dv; b.y = xi[5] * dv; b.z = xi[6] * dv; b.w = 0.0f;
    reinterpret_cast<float4*>(d_xd)[i * 2]     = a;
    reinterpret_cast<float4*>(d_xd)[i * 2 + 1] = b;
}

// ---- fused gather7 + dense transform: one warp per node --------------------

__global__ void k_transform(const float* __restrict__ W1,
                            const float* __restrict__ b1,
                            const float* __restrict__ W2, int n) {
    __shared__ float W1s[7 * F1];
    __shared__ float b1s[F1];
    __shared__ float W2s[F1 * F2];
    __shared__ float hs[8][F1];

    for (int i = threadIdx.x; i < 7 * F1;  i += blockDim.x) W1s[i] = W1[i];
    for (int i = threadIdx.x; i < F1;      i += blockDim.x) b1s[i] = b1[i];
    for (int i = threadIdx.x; i < F1 * F2; i += blockDim.x) W2s[i] = W2[i];
    __syncthreads();

    int warp = threadIdx.x >> 5;
    int lane = threadIdx.x & 31;
    int node = blockIdx.x * 8 + warp;
    if (node >= n) return;

    int beg = d_rowptr[node], end = d_rowptr[node + 1];
    int sub = lane >> 3;       // neighbor slot 0..3
    int f   = lane & 7;        // feature 0..7

    float acc = 0.0f;
    for (int i = beg + sub; i < end; i += 4)
        acc += d_xd[(long long)d_col[i] * 8 + f];
    acc += __shfl_down_sync(0xffffffffu, acc, 16);
    acc += __shfl_down_sync(0xffffffffu, acc, 8);

    float pv = 0.0f;
    if (lane < 8) pv = acc + d_xd[(long long)node * 8 + lane];  // self loop

    float dv = d_dinv[node];
    float a0 = 0.0f, a1 = 0.0f;
    #pragma unroll
    for (int k = 0; k < 7; k++) {
        float pk = __shfl_sync(0xffffffffu, pv, k);
        a0 += pk * W1s[k * F1 + lane];
        a1 += pk * W1s[k * F1 + 32 + lane];
    }
    hs[warp][lane]      = fmaxf(dv * a0 + b1s[lane],      0.0f);
    hs[warp][lane + 32] = fmaxf(dv * a1 + b1s[lane + 32], 0.0f);
    __syncwarp();

    float a = 0.0f;
    #pragma unroll
    for (int k = 0; k < F1; k++)
        a += hs[warp][k] * W2s[k * F2 + lane];

    d_g2[(long long)node * F2 + lane] = a * dv;
}

// ---- fused gather32 + classifier + log_softmax: one warp per node ----------

__global__ void k_final(const float* __restrict__ b2,
                        const float* __restrict__ Wc,
                        const float* __restrict__ bc,
                        float* __restrict__ out, int n) {
    int warp = threadIdx.x >> 5;
    int lane = threadIdx.x & 31;
    int node = blockIdx.x * 8 + warp;
    if (node >= n) return;

    float acc = d_g2[(long long)node * F2 + lane];  // self loop
    int beg = d_rowptr[node], end = d_rowptr[node + 1];
    int i = beg;
    for (; i + 4 <= end; i += 4) {
        int n0 = d_col[i], n1 = d_col[i + 1], n2 = d_col[i + 2], n3 = d_col[i + 3];
        float v0 = d_g2[(long long)n0 * F2 + lane];
        float v1 = d_g2[(long long)n1 * F2 + lane];
        float v2 = d_g2[(long long)n2 * F2 + lane];
        float v3 = d_g2[(long long)n3 * F2 + lane];
        acc += v0 + v1 + v2 + v3;
    }
    for (; i < end; i++)
        acc += d_g2[(long long)d_col[i] * F2 + lane];

    float h = fmaxf(d_dinv[node] * acc + b2[lane], 0.0f);
    float l0 = h * Wc[lane * 2];
    float l1 = h * Wc[lane * 2 + 1];
    #pragma unroll
    for (int off = 16; off > 0; off >>= 1) {
        l0 += __shfl_down_sync(0xffffffffu, l0, off);
        l1 += __shfl_down_sync(0xffffffffu, l1, off);
    }
    if (lane == 0) {
        l0 += bc[0];
        l1 += bc[1];
        float m   = fmaxf(l0, l1);
        float lse = m + logf(expf(l0 - m) + expf(l1 - m));
        out[(long long)node * 2]     = l0 - lse;
        out[(long long)node * 2 + 1] = l1 - lse;
    }
}

// ---- launch ----------------------------------------------------------------

extern "C" void kernel_launch(void* const* d_in, const int* in_sizes, int n_in,
                              void* d_out, int out_size) {
    const float* x  = (const float*)d_in[0];
    const int*   ei = (const int*)  d_in[1];
    const float* W1 = (const float*)d_in[2];
    const float* b1 = (const float*)d_in[3];
    const float* W2 = (const float*)d_in[4];
    const float* b2 = (const float*)d_in[5];
    const float* Wc = (const float*)d_in[6];
    const float* bc = (const float*)d_in[7];
    float* out = (float*)d_out;

    int n = in_sizes[0] / 7;     // 100000
    int E = in_sizes[1] / 2;     // 1600000
    const int* src = ei;
    const int* dst = ei + E;

    const int T = 256;
    int nblk = (n + SCAN_CHUNK - 1) / SCAN_CHUNK;   // 98

    k_zero_cnt<<<(n + T - 1) / T, T>>>(n);
    k_count   <<<(E + T - 1) / T, T>>>(dst, E);

    k_scan_partial<<<nblk, SCAN_T>>>(n);
    k_scan_top    <<<1, 128>>>(nblk, n, E);
    k_scan_apply  <<<nblk, SCAN_T>>>(n);

    k_prep<<<(n + T - 1) / T, T>>>(x, n);
    k_fill<<<(E + T - 1) / T, T>>>(src, dst, E);

    k_transform<<<(n + 7) / 8, T>>>(W1, b1, W2, n);
    k_final    <<<(n + 7) / 8, T>>>(b2, Wc, bc, out, n);
}

// round 5
// speedup vs baseline: 1.6954x; 1.0149x over previous
#include <cuda_runtime.h>

// FakeReviewGNN: 2-layer GCN, N=100000, 7 -> 64 -> 32 -> 2.
// Per-call CSR (counting sort by dst) -> atomic-free gather aggregation.
// 6-kernel pipeline (launch-floor minimized):
//   k_count        : histogram of dst (int4-vectorized, cnt pre-zeroed by k_final)
//   k_scan_partial : per-block sums of cnt
//   k_scan_apply   : exclusive scan (redundant top-scan per block) + rowptr/wcur
//                    + fused prep (dinv = rsqrt(cnt+1), xd = x*dinv padded 7->8)
//   k_fill         : counting-sort edges into col[] (int4-vectorized)
//   k_transform    : gather7 + (p@W1 -> relu -> @W2)*dinv -> g2
//   k_final        : gather32 + relu + classifier + log_softmax + reset cnt

#define MAXN 100000
#define MAXE 1600000
#define F1 64
#define F2 32

#define SCAN_T 256
#define SCAN_C 4
#define SCAN_CHUNK (SCAN_T * SCAN_C)   // 1024

__device__ int   d_cnt   [MAXN];        // zero-init; k_final resets after use
__device__ int   d_rowptr[MAXN + 1];
__device__ int   d_wcur  [MAXN];
__device__ int   d_bsum  [256];
__device__ int   d_col   [MAXE];
__device__ float d_dinv  [MAXN];
__device__ __align__(128) float d_xd[MAXN * 8];
__device__ __align__(128) float d_g2[MAXN * F2];

// ---- histogram (cnt assumed zero on entry) ---------------------------------

__global__ void k_count_v4(const int4* __restrict__ dst4, int E4) {
    int i = blockIdx.x * blockDim.x + threadIdx.x;
    if (i >= E4) return;
    int4 d = dst4[i];
    atomicAdd(&d_cnt[d.x], 1);
    atomicAdd(&d_cnt[d.y], 1);
    atomicAdd(&d_cnt[d.z], 1);
    atomicAdd(&d_cnt[d.w], 1);
}

__global__ void k_count_sc(const int* __restrict__ dst, int E) {
    int i = blockIdx.x * blockDim.x + threadIdx.x;
    if (i < E) atomicAdd(&d_cnt[dst[i]], 1);
}

// ---- scan phase 1: per-block partial sums ----------------------------------

__global__ void k_scan_partial(int n) {
    __shared__ int sh[SCAN_T];
    int base = blockIdx.x * SCAN_CHUNK + threadIdx.x * SCAN_C;
    int s = 0;
    #pragma unroll
    for (int j = 0; j < SCAN_C; j++) {
        int idx = base + j;
        if (idx < n) s += d_cnt[idx];
    }
    sh[threadIdx.x] = s;
    __syncthreads();
    for (int off = SCAN_T / 2; off > 0; off >>= 1) {
        if (threadIdx.x < off) sh[threadIdx.x] += sh[threadIdx.x + off];
        __syncthreads();
    }
    if (threadIdx.x == 0) d_bsum[blockIdx.x] = sh[0];
}

// ---- scan phase 2: apply + fused prep --------------------------------------

__global__ void k_scan_apply(const float* __restrict__ x, int n, int E) {
    __shared__ int sh[SCAN_T];
    __shared__ int s_boff;
    int tid = threadIdx.x;

    // Redundant top-scan: this block's offset = sum of bsum[j], j < blockIdx.x
    {
        int v = (tid < blockIdx.x) ? d_bsum[tid] : 0;   // blockIdx.x <= 97 < 256
        sh[tid] = v;
        __syncthreads();
        for (int off = SCAN_T / 2; off > 0; off >>= 1) {
            if (tid < off) sh[tid] += sh[tid + off];
            __syncthreads();
        }
        if (tid == 0) s_boff = sh[0];
        __syncthreads();
    }

    int base = blockIdx.x * SCAN_CHUNK + tid * SCAN_C;
    int loc[SCAN_C];
    int s = 0;
    #pragma unroll
    for (int j = 0; j < SCAN_C; j++) {
        int idx = base + j;
        loc[j] = (idx < n) ? d_cnt[idx] : 0;
        s += loc[j];
    }
    sh[tid] = s;
    __syncthreads();
    for (int off = 1; off < SCAN_T; off <<= 1) {
        int t = (tid >= off) ? sh[tid - off] : 0;
        __syncthreads();
        sh[tid] += t;
        __syncthreads();
    }
    int run = s_boff + sh[tid] - s;   // exclusive prefix for this thread's chunk

    #pragma unroll
    for (int j = 0; j < SCAN_C; j++) {
        int idx = base + j;
        if (idx < n) {
            d_rowptr[idx] = run;
            d_wcur[idx]   = run;
            run += loc[j];
            // fused prep
            float dv = rsqrtf((float)(loc[j] + 1));   // +1 self loop
            d_dinv[idx] = dv;
            const float* xi = x + (long long)idx * 7;
            float4 a, b;
            a.x = xi[0] * dv; a.y = xi[1] * dv; a.z = xi[2] * dv; a.w = xi[3] * dv;
            b.x = xi[4] * dv; b.y = xi[5] * dv; b.z = xi[6] * dv; b.w = 0.0f;
            reinterpret_cast<float4*>(d_xd)[idx * 2]     = a;
            reinterpret_cast<float4*>(d_xd)[idx * 2 + 1] = b;
        }
    }
    if (blockIdx.x == 0 && tid == 0) d_rowptr[n] = E;
}

// ---- CSR fill ---------------------------------------------------------------

__global__ void k_fill_v4(const int4* __restrict__ src4,
                          const int4* __restrict__ dst4, int E4) {
    int i = blockIdx.x * blockDim.x + threadIdx.x;
    if (i >= E4) return;
    int4 sv = src4[i];
    int4 dv = dst4[i];
    d_col[atomicAdd(&d_wcur[dv.x], 1)] = sv.x;
    d_col[atomicAdd(&d_wcur[dv.y], 1)] = sv.y;
    d_col[atomicAdd(&d_wcur[dv.z], 1)] = sv.z;
    d_col[atomicAdd(&d_wcur[dv.w], 1)] = sv.w;
}

__global__ void k_fill_sc(const int* __restrict__ src,
                          const int* __restrict__ dst, int E) {
    int e = blockIdx.x * blockDim.x + threadIdx.x;
    if (e >= E) return;
    d_col[atomicAdd(&d_wcur[dst[e]], 1)] = src[e];
}

// ---- fused gather7 + dense transform: one warp per node --------------------

__global__ void k_transform(const float* __restrict__ W1,
                            const float* __restrict__ b1,
                            const float* __restrict__ W2, int n) {
    __shared__ float W1s[7 * F1];
    __shared__ float b1s[F1];
    __shared__ float W2s[F1 * F2];
    __shared__ float hs[8][F1];

    for (int i = threadIdx.x; i < 7 * F1;  i += blockDim.x) W1s[i] = W1[i];
    for (int i = threadIdx.x; i < F1;      i += blockDim.x) b1s[i] = b1[i];
    for (int i = threadIdx.x; i < F1 * F2; i += blockDim.x) W2s[i] = W2[i];
    __syncthreads();

    int warp = threadIdx.x >> 5;
    int lane = threadIdx.x & 31;
    int node = blockIdx.x * 8 + warp;
    if (node >= n) return;

    int beg = d_rowptr[node], end = d_rowptr[node + 1];
    int sub = lane >> 3;       // neighbor slot 0..3
    int f   = lane & 7;        // feature 0..7

    float acc = 0.0f;
    int i = beg + sub;
    for (; i + 4 < end; i += 8) {   // 2 slots in flight -> 8 gathers/warp-iter
        int c0 = d_col[i];
        int c1 = d_col[i + 4];
        float v0 = __ldg(&d_xd[(long long)c0 * 8 + f]);
        float v1 = __ldg(&d_xd[(long long)c1 * 8 + f]);
        acc += v0 + v1;
    }
    if (i < end)
        acc += __ldg(&d_xd[(long long)d_col[i] * 8 + f]);

    acc += __shfl_down_sync(0xffffffffu, acc, 16);
    acc += __shfl_down_sync(0xffffffffu, acc, 8);

    float pv = 0.0f;
    if (lane < 8) pv = acc + d_xd[(long long)node * 8 + lane];  // self loop

    float dv = d_dinv[node];
    float a0 = 0.0f, a1 = 0.0f;
    #pragma unroll
    for (int k = 0; k < 7; k++) {
        float pk = __shfl_sync(0xffffffffu, pv, k);
        a0 += pk * W1s[k * F1 + lane];
        a1 += pk * W1s[k * F1 + 32 + lane];
    }
    hs[warp][lane]      = fmaxf(dv * a0 + b1s[lane],      0.0f);
    hs[warp][lane + 32] = fmaxf(dv * a1 + b1s[lane + 32], 0.0f);
    __syncwarp();

    float a = 0.0f;
    #pragma unroll
    for (int k = 0; k < F1; k++)
        a += hs[warp][k] * W2s[k * F2 + lane];

    d_g2[(long long)node * F2 + lane] = a * dv;
}

// ---- fused gather32 + classifier + log_softmax + cnt reset -----------------

__global__ void k_final(const float* __restrict__ b2,
                        const float* __restrict__ Wc,
                        const float* __restrict__ bc,
                        float* __restrict__ out, int n) {
    int warp = threadIdx.x >> 5;
    int lane = threadIdx.x & 31;
    int node = blockIdx.x * 8 + warp;
    if (node >= n) return;

    float acc = d_g2[(long long)node * F2 + lane];  // self loop
    int beg = d_rowptr[node], end = d_rowptr[node + 1];
    int i = beg;
    for (; i + 8 <= end; i += 8) {                  // 8 gathers in flight
        int c0 = d_col[i],     c1 = d_col[i + 1];
        int c2 = d_col[i + 2], c3 = d_col[i + 3];
        int c4 = d_col[i + 4], c5 = d_col[i + 5];
        int c6 = d_col[i + 6], c7 = d_col[i + 7];
        float v0 = __ldg(&d_g2[(long long)c0 * F2 + lane]);
        float v1 = __ldg(&d_g2[(long long)c1 * F2 + lane]);
        float v2 = __ldg(&d_g2[(long long)c2 * F2 + lane]);
        float v3 = __ldg(&d_g2[(long long)c3 * F2 + lane]);
        float v4 = __ldg(&d_g2[(long long)c4 * F2 + lane]);
        float v5 = __ldg(&d_g2[(long long)c5 * F2 + lane]);
        float v6 = __ldg(&d_g2[(long long)c6 * F2 + lane]);
        float v7 = __ldg(&d_g2[(long long)c7 * F2 + lane]);
        acc += ((v0 + v1) + (v2 + v3)) + ((v4 + v5) + (v6 + v7));
    }
    for (; i < end; i++)
        acc += __ldg(&d_g2[(long long)d_col[i] * F2 + lane]);

    float h = fmaxf(d_dinv[node] * acc + b2[lane], 0.0f);
    float l0 = h * Wc[lane * 2];
    float l1 = h * Wc[lane * 2 + 1];
    #pragma unroll
    for (int off = 16; off > 0; off >>= 1) {
        l0 += __shfl_down_sync(0xffffffffu, l0, off);
        l1 += __shfl_down_sync(0xffffffffu, l1, off);
    }
    if (lane == 0) {
        l0 += bc[0];
        l1 += bc[1];
        float m   = fmaxf(l0, l1);
        float lse = m + logf(expf(l0 - m) + expf(l1 - m));
        out[(long long)node * 2]     = l0 - lse;
        out[(long long)node * 2 + 1] = l1 - lse;
        d_cnt[node] = 0;   // reset histogram for next replay (deterministic)
    }
}

// ---- launch ----------------------------------------------------------------

extern "C" void kernel_launch(void* const* d_in, const int* in_sizes, int n_in,
                              void* d_out, int out_size) {
    const float* x  = (const float*)d_in[0];
    const int*   ei = (const int*)  d_in[1];
    const float* W1 = (const float*)d_in[2];
    const float* b1 = (const float*)d_in[3];
    const float* W2 = (const float*)d_in[4];
    const float* b2 = (const float*)d_in[5];
    const float* Wc = (const float*)d_in[6];
    const float* bc = (const float*)d_in[7];
    float* out = (float*)d_out;

    int n = in_sizes[0] / 7;     // 100000
    int E = in_sizes[1] / 2;     // 1600000
    const int* src = ei;
    const int* dst = ei + E;

    const int T = 256;
    int nblk = (n + SCAN_CHUNK - 1) / SCAN_CHUNK;   // 98

    bool vec_ok = (E % 4 == 0) && ((((unsigned long long)src) & 15ull) == 0)
                                && ((((unsigned long long)dst) & 15ull) == 0);

    if (vec_ok) {
        int E4 = E / 4;
        k_count_v4<<<(E4 + T - 1) / T, T>>>((const int4*)dst, E4);
    } else {
        k_count_sc<<<(E + T - 1) / T, T>>>(dst, E);
    }

    k_scan_partial<<<nblk, SCAN_T>>>(n);
    k_scan_apply  <<<nblk, SCAN_T>>>(x, n, E);

    if (vec_ok) {
        int E4 = E / 4;
        k_fill_v4<<<(E4 + T - 1) / T, T>>>((const int4*)src, (const int4*)dst, E4);
    } else {
        k_fill_sc<<<(E + T - 1) / T, T>>>(src, dst, E);
    }

    k_transform<<<(n + 7) / 8, T>>>(W1, b1, W2, n);
    k_final    <<<(n + 7) / 8, T>>>(b2, Wc, bc, out, n);
}